// round 10
// baseline (speedup 1.0000x reference)
#include <cuda_runtime.h>

#define BC      128            // B*C = 8*16
#define B_DIM   8
#define C_DIM   16
#define HW      147456         // 384*384
#define HW4     36864          // HW/4 (float4 per class)
#define SPLIT   6              // blocks per class
#define BLK4    (HW4 / SPLIT)  // 6144 float4 per block per array
#define HALF4   (BLK4 / 2)     // 3072
#define NTHREADS 256
#define ITERS   (HALF4 / NTHREADS)   // 12
#define NBLOCKS (BC * SPLIT)         // 768
#define PF      3              // prefetch distance (iterations)

#define ALPHA   0.05f
#define SMOOTH  1e-6f

// scratch: [NBLOCKS][5] partials: {sum_d2t, sum_d2, sum_t, max_t, max_p}
__device__ float g_part[NBLOCKS * 5];
__device__ int   g_count = 0;

__device__ __forceinline__ void pf_l2(const void* p) {
    asm volatile("prefetch.global.L2 [%0];" :: "l"(p));
}

__global__ __launch_bounds__(NTHREADS)
void fused_kernel(const float4* __restrict__ no,
                  const float4* __restrict__ tg,
                  const float4* __restrict__ mp,
                  float* __restrict__ out)
{
    const int cls  = blockIdx.x / SPLIT;
    const int part = blockIdx.x % SPLIT;
    const long base = (long)cls * HW4 + (long)part * BLK4;

    const int wid = threadIdx.x >> 5;
    const int lid = threadIdx.x & 31;
    const int NW  = NTHREADS / 32;

    float s_d2t = 0.f, s_d2 = 0.f, s_t = 0.f;
    float mxt = -1e30f;

    const float4* tl = tg + base + threadIdx.x;
    const float4* th = tg + base + HALF4 + threadIdx.x;
    const float4* nl = no + base + threadIdx.x;
    const float4* nh = no + base + HALF4 + threadIdx.x;

    // prime the L2 with the first PF iterations' lines
    #pragma unroll
    for (int k = 0; k < PF; k++) {
        const int idx = k * NTHREADS;
        pf_l2(tl + idx); pf_l2(th + idx); pf_l2(nl + idx); pf_l2(nh + idx);
    }

    // 4 independent load streams per iteration + L2 prefetch PF iters ahead
    for (int k = 0; k < ITERS; k++) {
        const int idx = k * NTHREADS;
        float4 t0 = tl[idx];
        float4 t1 = th[idx];
        float4 n0 = nl[idx];
        float4 n1 = nh[idx];

        if (k + PF < ITERS) {
            const int pidx = (k + PF) * NTHREADS;
            pf_l2(tl + pidx); pf_l2(th + pidx);
            pf_l2(nl + pidx); pf_l2(nh + pidx);
        }

        float d;
        d = t0.x - n0.x; float a0 = d * d;
        d = t0.y - n0.y; float a1 = d * d;
        d = t0.z - n0.z; float a2 = d * d;
        d = t0.w - n0.w; float a3 = d * d;
        s_d2  += a0 + a1 + a2 + a3;
        s_d2t += a0 * t0.x + a1 * t0.y + a2 * t0.z + a3 * t0.w;
        s_t   += t0.x + t0.y + t0.z + t0.w;
        mxt = fmaxf(mxt, fmaxf(fmaxf(t0.x, t0.y), fmaxf(t0.z, t0.w)));

        d = t1.x - n1.x; float b0 = d * d;
        d = t1.y - n1.y; float b1 = d * d;
        d = t1.z - n1.z; float b2 = d * d;
        d = t1.w - n1.w; float b3 = d * d;
        s_d2  += b0 + b1 + b2 + b3;
        s_d2t += b0 * t1.x + b1 * t1.y + b2 * t1.z + b3 * t1.w;
        s_t   += t1.x + t1.y + t1.z + t1.w;
        mxt = fmaxf(mxt, fmaxf(fmaxf(t1.x, t1.y), fmaxf(t1.z, t1.w)));
    }

    #pragma unroll
    for (int off = 16; off > 0; off >>= 1) {
        s_d2t += __shfl_xor_sync(0xffffffff, s_d2t, off);
        s_d2  += __shfl_xor_sync(0xffffffff, s_d2,  off);
        s_t   += __shfl_xor_sync(0xffffffff, s_t,   off);
        mxt = fmaxf(mxt, __shfl_xor_sync(0xffffffff, mxt, off));
    }

    __shared__ float sh[NTHREADS / 32][4];
    __shared__ float sh_blkmax;
    if (lid == 0) {
        sh[wid][0] = s_d2t; sh[wid][1] = s_d2; sh[wid][2] = s_t; sh[wid][3] = mxt;
    }
    __syncthreads();

    if (wid == 0) {
        float v0 = (lid < NW) ? sh[lid][0] : 0.f;
        float v1 = (lid < NW) ? sh[lid][1] : 0.f;
        float v2 = (lid < NW) ? sh[lid][2] : 0.f;
        float v3 = (lid < NW) ? sh[lid][3] : -1e30f;
        #pragma unroll
        for (int off = 4; off > 0; off >>= 1) {
            v0 += __shfl_xor_sync(0xffffffff, v0, off);
            v1 += __shfl_xor_sync(0xffffffff, v1, off);
            v2 += __shfl_xor_sync(0xffffffff, v2, off);
            v3 = fmaxf(v3, __shfl_xor_sync(0xffffffff, v3, off));
        }
        if (lid == 0) {
            sh[0][0] = v0; sh[0][1] = v1; sh[0][2] = v2;
            sh_blkmax = v3;
        }
    }
    __syncthreads();

    // rare pass: mp only matters if this block's target region is all-zero
    // (if any t>0, the class is active and this block's mxp is never consulted)
    float mxp = -1e30f;
    if (sh_blkmax == 0.0f) {
        const float4* pp = mp + base + threadIdx.x;
        for (int k = 0; k < BLK4 / NTHREADS; k++) {
            float4 p = pp[k * NTHREADS];
            mxp = fmaxf(mxp, fmaxf(fmaxf(p.x, p.y), fmaxf(p.z, p.w)));
        }
        #pragma unroll
        for (int off = 16; off > 0; off >>= 1)
            mxp = fmaxf(mxp, __shfl_xor_sync(0xffffffff, mxp, off));
        __shared__ float shp[NTHREADS / 32];
        if (lid == 0) shp[wid] = mxp;
        __syncthreads();
        if (wid == 0) {
            float v = (lid < NW) ? shp[lid] : -1e30f;
            #pragma unroll
            for (int off = 4; off > 0; off >>= 1)
                v = fmaxf(v, __shfl_xor_sync(0xffffffff, v, off));
            mxp = v;
        }
    }

    __shared__ bool s_last;
    if (threadIdx.x == 0) {
        float* dst = &g_part[(long)blockIdx.x * 5];
        dst[0] = sh[0][0]; dst[1] = sh[0][1]; dst[2] = sh[0][2];
        dst[3] = sh_blkmax; dst[4] = mxp;
        __threadfence();
        int old = atomicAdd(&g_count, 1);
        s_last = (old == NBLOCKS - 1);
    }
    __syncthreads();

    if (!s_last) return;

    // ---- fused epilogue: last block reduces all partials ----
    __shared__ float losses[BC];
    __shared__ float imgl[B_DIM];

    if (threadIdx.x < BC) {
        const int c = threadIdx.x;
        float a_d2t = 0.f, a_d2 = 0.f, a_t = 0.f;
        float a_mt = -1e30f, a_mp = -1e30f;
        #pragma unroll
        for (int j = 0; j < SPLIT; j++) {
            const float* src = &g_part[(long)(c * SPLIT + j) * 5];
            a_d2t += __ldcg(src + 0);
            a_d2  += __ldcg(src + 1);
            a_t   += __ldcg(src + 2);
            a_mt = fmaxf(a_mt, __ldcg(src + 3));
            a_mp = fmaxf(a_mp, __ldcg(src + 4));
        }
        float m1 = a_d2t;
        float m2 = a_d2 - a_d2t;
        float d1 = a_t;
        float d2 = (float)HW - a_t;
        float loss = ALPHA * m1 / (d1 + SMOOTH) + (1.0f - ALPHA) * m2 / (d2 + SMOOTH);
        bool active = !((a_mt == 0.0f) && (a_mp == 0.0f));
        losses[c] = active ? loss : 0.0f;
    }
    __syncthreads();

    if (threadIdx.x < B_DIM) {
        float s = 0.f, cnt = 0.f;
        #pragma unroll
        for (int c = 0; c < C_DIM; c++) {
            float v = losses[threadIdx.x * C_DIM + c];
            s += v;
            if (v != 0.0f) cnt += 1.0f;
        }
        imgl[threadIdx.x] = s / cnt;
    }
    __syncthreads();

    if (threadIdx.x == 0) {
        float s = 0.f;
        #pragma unroll
        for (int b = 0; b < B_DIM; b++) s += imgl[b];
        out[0] = s / (float)B_DIM;
        g_count = 0;   // reset for next graph replay (deterministic)
    }
}

extern "C" void kernel_launch(void* const* d_in, const int* in_sizes, int n_in,
                              void* d_out, int out_size)
{
    const float4* no = (const float4*)d_in[0];   // net_out
    const float4* tg = (const float4*)d_in[1];   // target
    const float4* mp = (const float4*)d_in[2];   // max_positiones

    fused_kernel<<<NBLOCKS, NTHREADS>>>(no, tg, mp, (float*)d_out);
}

// round 11
// speedup vs baseline: 1.0290x; 1.0290x over previous
#include <cuda_runtime.h>
#include <cstdint>

#define BC      128            // B*C = 8*16
#define B_DIM   8
#define C_DIM   16
#define HW      147456         // 384*384
#define HW4     36864          // HW/4 (float4 per class)
#define SPLIT   12             // blocks per class
#define BLK4    (HW4 / SPLIT)  // 3072 float4 per block per array
#define NTHREADS 256
#define ITERS   (BLK4 / NTHREADS)    // 12
#define NBLOCKS (BC * SPLIT)         // 1536
#define STAGES  4

#define ALPHA   0.05f
#define SMOOTH  1e-6f

// scratch: [NBLOCKS][5] partials: {sum_d2t, sum_d2, sum_t, max_t, max_p}
__device__ float g_part[NBLOCKS * 5];
__device__ int   g_count = 0;

__device__ __forceinline__ uint32_t smem_u32(const void* p) {
    return (uint32_t)__cvta_generic_to_shared(p);
}
#define CP_ASYNC16(dst, src) \
    asm volatile("cp.async.cg.shared.global [%0], [%1], 16;" :: "r"(dst), "l"(src) : "memory")
#define CP_COMMIT() asm volatile("cp.async.commit_group;" ::: "memory")
#define CP_WAIT(n)  asm volatile("cp.async.wait_group %0;" :: "n"(n) : "memory")

__global__ __launch_bounds__(NTHREADS)
void fused_kernel(const float4* __restrict__ no,
                  const float4* __restrict__ tg,
                  const float4* __restrict__ mp,
                  float* __restrict__ out)
{
    // per-thread private ring slots: thread i owns sm_t[s][i], sm_n[s][i].
    // 2 * 4 * 256 * 16B = 32KB -> ~7 CTAs/SM, ~224KB cp.async in flight per SM
    __shared__ __align__(16) float4 sm_t[STAGES][NTHREADS];
    __shared__ __align__(16) float4 sm_n[STAGES][NTHREADS];

    const int cls  = blockIdx.x / SPLIT;
    const int part = blockIdx.x % SPLIT;
    const long base = (long)cls * HW4 + (long)part * BLK4;

    const int wid = threadIdx.x >> 5;
    const int lid = threadIdx.x & 31;
    const int NW  = NTHREADS / 32;

    const float4* tp = tg + base + threadIdx.x;
    const float4* np = no + base + threadIdx.x;

    uint32_t dst_t[STAGES], dst_n[STAGES];
    #pragma unroll
    for (int s = 0; s < STAGES; s++) {
        dst_t[s] = smem_u32(&sm_t[s][threadIdx.x]);
        dst_n[s] = smem_u32(&sm_n[s][threadIdx.x]);
    }

    // prologue: fill the ring (fire-and-forget, no registers consumed)
    #pragma unroll
    for (int s = 0; s < STAGES; s++) {
        CP_ASYNC16(dst_t[s], tp + s * NTHREADS);
        CP_ASYNC16(dst_n[s], np + s * NTHREADS);
        CP_COMMIT();
    }

    float s_d2t = 0.f, s_d2 = 0.f, s_t = 0.f;
    float mxt = -1e30f;

    #pragma unroll
    for (int k = 0; k < ITERS; k++) {
        const int s = k & (STAGES - 1);
        CP_WAIT(STAGES - 1);           // own group k complete (per-thread state)

        float4 t = sm_t[s][threadIdx.x];
        float4 n = sm_n[s][threadIdx.x];

        // refill this slot for iteration k+STAGES; always commit (empty
        // groups in the tail keep one-group-per-iteration accounting exact)
        if (k + STAGES < ITERS) {
            CP_ASYNC16(dst_t[s], tp + (k + STAGES) * NTHREADS);
            CP_ASYNC16(dst_n[s], np + (k + STAGES) * NTHREADS);
        }
        CP_COMMIT();

        float d;
        d = t.x - n.x; float a0 = d * d;
        d = t.y - n.y; float a1 = d * d;
        d = t.z - n.z; float a2 = d * d;
        d = t.w - n.w; float a3 = d * d;
        s_d2  += a0 + a1 + a2 + a3;
        s_d2t += a0 * t.x + a1 * t.y + a2 * t.z + a3 * t.w;
        s_t   += t.x + t.y + t.z + t.w;
        mxt = fmaxf(mxt, fmaxf(fmaxf(t.x, t.y), fmaxf(t.z, t.w)));
    }
    CP_WAIT(0);

    #pragma unroll
    for (int off = 16; off > 0; off >>= 1) {
        s_d2t += __shfl_xor_sync(0xffffffff, s_d2t, off);
        s_d2  += __shfl_xor_sync(0xffffffff, s_d2,  off);
        s_t   += __shfl_xor_sync(0xffffffff, s_t,   off);
        mxt = fmaxf(mxt, __shfl_xor_sync(0xffffffff, mxt, off));
    }

    __shared__ float sh[NTHREADS / 32][4];
    __shared__ float sh_blkmax;
    if (lid == 0) {
        sh[wid][0] = s_d2t; sh[wid][1] = s_d2; sh[wid][2] = s_t; sh[wid][3] = mxt;
    }
    __syncthreads();

    if (wid == 0) {
        float v0 = (lid < NW) ? sh[lid][0] : 0.f;
        float v1 = (lid < NW) ? sh[lid][1] : 0.f;
        float v2 = (lid < NW) ? sh[lid][2] : 0.f;
        float v3 = (lid < NW) ? sh[lid][3] : -1e30f;
        #pragma unroll
        for (int off = 4; off > 0; off >>= 1) {
            v0 += __shfl_xor_sync(0xffffffff, v0, off);
            v1 += __shfl_xor_sync(0xffffffff, v1, off);
            v2 += __shfl_xor_sync(0xffffffff, v2, off);
            v3 = fmaxf(v3, __shfl_xor_sync(0xffffffff, v3, off));
        }
        if (lid == 0) {
            sh[0][0] = v0; sh[0][1] = v1; sh[0][2] = v2;
            sh_blkmax = v3;
        }
    }
    __syncthreads();

    // rare pass: mp only matters if this block's target region is all-zero
    // (if any t>0, the class is active and this block's mxp is never consulted)
    float mxp = -1e30f;
    if (sh_blkmax == 0.0f) {
        const float4* pp = mp + base + threadIdx.x;
        for (int k = 0; k < ITERS; k++) {
            float4 p = pp[k * NTHREADS];
            mxp = fmaxf(mxp, fmaxf(fmaxf(p.x, p.y), fmaxf(p.z, p.w)));
        }
        #pragma unroll
        for (int off = 16; off > 0; off >>= 1)
            mxp = fmaxf(mxp, __shfl_xor_sync(0xffffffff, mxp, off));
        __shared__ float shp[NTHREADS / 32];
        if (lid == 0) shp[wid] = mxp;
        __syncthreads();
        if (wid == 0) {
            float v = (lid < NW) ? shp[lid] : -1e30f;
            #pragma unroll
            for (int off = 4; off > 0; off >>= 1)
                v = fmaxf(v, __shfl_xor_sync(0xffffffff, v, off));
            mxp = v;
        }
    }

    __shared__ bool s_last;
    if (threadIdx.x == 0) {
        float* dst = &g_part[(long)blockIdx.x * 5];
        dst[0] = sh[0][0]; dst[1] = sh[0][1]; dst[2] = sh[0][2];
        dst[3] = sh_blkmax; dst[4] = mxp;
        __threadfence();
        int old = atomicAdd(&g_count, 1);
        s_last = (old == NBLOCKS - 1);
    }
    __syncthreads();

    if (!s_last) return;

    // ---- fused epilogue: last block reduces all partials ----
    __shared__ float losses[BC];
    __shared__ float imgl[B_DIM];

    if (threadIdx.x < BC) {
        const int c = threadIdx.x;
        float a_d2t = 0.f, a_d2 = 0.f, a_t = 0.f;
        float a_mt = -1e30f, a_mp = -1e30f;
        #pragma unroll
        for (int j = 0; j < SPLIT; j++) {
            const float* src = &g_part[(long)(c * SPLIT + j) * 5];
            a_d2t += __ldcg(src + 0);
            a_d2  += __ldcg(src + 1);
            a_t   += __ldcg(src + 2);
            a_mt = fmaxf(a_mt, __ldcg(src + 3));
            a_mp = fmaxf(a_mp, __ldcg(src + 4));
        }
        float m1 = a_d2t;
        float m2 = a_d2 - a_d2t;
        float d1 = a_t;
        float d2 = (float)HW - a_t;
        float loss = ALPHA * m1 / (d1 + SMOOTH) + (1.0f - ALPHA) * m2 / (d2 + SMOOTH);
        bool active = !((a_mt == 0.0f) && (a_mp == 0.0f));
        losses[c] = active ? loss : 0.0f;
    }
    __syncthreads();

    if (threadIdx.x < B_DIM) {
        float s = 0.f, cnt = 0.f;
        #pragma unroll
        for (int c = 0; c < C_DIM; c++) {
            float v = losses[threadIdx.x * C_DIM + c];
            s += v;
            if (v != 0.0f) cnt += 1.0f;
        }
        imgl[threadIdx.x] = s / cnt;
    }
    __syncthreads();

    if (threadIdx.x == 0) {
        float s = 0.f;
        #pragma unroll
        for (int b = 0; b < B_DIM; b++) s += imgl[b];
        out[0] = s / (float)B_DIM;
        g_count = 0;   // reset for next graph replay (deterministic)
    }
}

extern "C" void kernel_launch(void* const* d_in, const int* in_sizes, int n_in,
                              void* d_out, int out_size)
{
    const float4* no = (const float4*)d_in[0];   // net_out
    const float4* tg = (const float4*)d_in[1];   // target
    const float4* mp = (const float4*)d_in[2];   // max_positiones

    fused_kernel<<<NBLOCKS, NTHREADS>>>(no, tg, mp, (float*)d_out);
}

// round 12
// speedup vs baseline: 1.1240x; 1.0923x over previous
#include <cuda_runtime.h>

#define BC      128            // B*C = 8*16
#define B_DIM   8
#define C_DIM   16
#define HW      147456         // 384*384
#define HW4     36864          // HW/4 (float4 per class)
#define SPLIT   6              // blocks per class
#define BLK4    (HW4 / SPLIT)  // 6144 float4 per block per array
#define THIRD4  (BLK4 / 3)     // 2048
#define NTHREADS 256
#define ITERS   (THIRD4 / NTHREADS)  // 8
#define NBLOCKS (BC * SPLIT)         // 768

#define ALPHA   0.05f
#define SMOOTH  1e-6f

// scratch: [NBLOCKS][5] partials: {sum_d2t, sum_d2, sum_t, max_t, max_p}
__device__ float g_part[NBLOCKS * 5];
__device__ int   g_count = 0;

__global__ __launch_bounds__(NTHREADS)
void fused_kernel(const float4* __restrict__ no,
                  const float4* __restrict__ tg,
                  const float4* __restrict__ mp,
                  float* __restrict__ out)
{
    const int cls  = blockIdx.x / SPLIT;
    const int part = blockIdx.x % SPLIT;
    const long base = (long)cls * HW4 + (long)part * BLK4;

    const int wid = threadIdx.x >> 5;
    const int lid = threadIdx.x & 31;
    const int NW  = NTHREADS / 32;

    float s_d2t = 0.f, s_d2 = 0.f, s_t = 0.f;
    float mxt = -1e30f;

    const float4* t0p = tg + base + threadIdx.x;
    const float4* t1p = t0p + THIRD4;
    const float4* t2p = t1p + THIRD4;
    const float4* n0p = no + base + threadIdx.x;
    const float4* n1p = n0p + THIRD4;
    const float4* n2p = n1p + THIRD4;

    // 6 independent load streams per iteration; natural compiler pipelining
    for (int k = 0; k < ITERS; k++) {
        const int idx = k * NTHREADS;
        float4 t0 = t0p[idx];
        float4 t1 = t1p[idx];
        float4 t2 = t2p[idx];
        float4 n0 = n0p[idx];
        float4 n1 = n1p[idx];
        float4 n2 = n2p[idx];

        float d;
        d = t0.x - n0.x; float a0 = d * d;
        d = t0.y - n0.y; float a1 = d * d;
        d = t0.z - n0.z; float a2 = d * d;
        d = t0.w - n0.w; float a3 = d * d;
        s_d2  += a0 + a1 + a2 + a3;
        s_d2t += a0 * t0.x + a1 * t0.y + a2 * t0.z + a3 * t0.w;
        s_t   += t0.x + t0.y + t0.z + t0.w;
        mxt = fmaxf(mxt, fmaxf(fmaxf(t0.x, t0.y), fmaxf(t0.z, t0.w)));

        d = t1.x - n1.x; float b0 = d * d;
        d = t1.y - n1.y; float b1 = d * d;
        d = t1.z - n1.z; float b2 = d * d;
        d = t1.w - n1.w; float b3 = d * d;
        s_d2  += b0 + b1 + b2 + b3;
        s_d2t += b0 * t1.x + b1 * t1.y + b2 * t1.z + b3 * t1.w;
        s_t   += t1.x + t1.y + t1.z + t1.w;
        mxt = fmaxf(mxt, fmaxf(fmaxf(t1.x, t1.y), fmaxf(t1.z, t1.w)));

        d = t2.x - n2.x; float c0 = d * d;
        d = t2.y - n2.y; float c1 = d * d;
        d = t2.z - n2.z; float c2 = d * d;
        d = t2.w - n2.w; float c3 = d * d;
        s_d2  += c0 + c1 + c2 + c3;
        s_d2t += c0 * t2.x + c1 * t2.y + c2 * t2.z + c3 * t2.w;
        s_t   += t2.x + t2.y + t2.z + t2.w;
        mxt = fmaxf(mxt, fmaxf(fmaxf(t2.x, t2.y), fmaxf(t2.z, t2.w)));
    }

    #pragma unroll
    for (int off = 16; off > 0; off >>= 1) {
        s_d2t += __shfl_xor_sync(0xffffffff, s_d2t, off);
        s_d2  += __shfl_xor_sync(0xffffffff, s_d2,  off);
        s_t   += __shfl_xor_sync(0xffffffff, s_t,   off);
        mxt = fmaxf(mxt, __shfl_xor_sync(0xffffffff, mxt, off));
    }

    __shared__ float sh[NTHREADS / 32][4];
    __shared__ float sh_blkmax;
    if (lid == 0) {
        sh[wid][0] = s_d2t; sh[wid][1] = s_d2; sh[wid][2] = s_t; sh[wid][3] = mxt;
    }
    __syncthreads();

    if (wid == 0) {
        float v0 = (lid < NW) ? sh[lid][0] : 0.f;
        float v1 = (lid < NW) ? sh[lid][1] : 0.f;
        float v2 = (lid < NW) ? sh[lid][2] : 0.f;
        float v3 = (lid < NW) ? sh[lid][3] : -1e30f;
        #pragma unroll
        for (int off = 4; off > 0; off >>= 1) {
            v0 += __shfl_xor_sync(0xffffffff, v0, off);
            v1 += __shfl_xor_sync(0xffffffff, v1, off);
            v2 += __shfl_xor_sync(0xffffffff, v2, off);
            v3 = fmaxf(v3, __shfl_xor_sync(0xffffffff, v3, off));
        }
        if (lid == 0) {
            sh[0][0] = v0; sh[0][1] = v1; sh[0][2] = v2;
            sh_blkmax = v3;
        }
    }
    __syncthreads();

    // rare pass: mp only matters if this block's target region is all-zero
    // (if any t>0, the class is active and this block's mxp is never consulted)
    float mxp = -1e30f;
    if (sh_blkmax == 0.0f) {
        const float4* pp = mp + base + threadIdx.x;
        for (int k = 0; k < BLK4 / NTHREADS; k++) {
            float4 p = pp[k * NTHREADS];
            mxp = fmaxf(mxp, fmaxf(fmaxf(p.x, p.y), fmaxf(p.z, p.w)));
        }
        #pragma unroll
        for (int off = 16; off > 0; off >>= 1)
            mxp = fmaxf(mxp, __shfl_xor_sync(0xffffffff, mxp, off));
        __shared__ float shp[NTHREADS / 32];
        if (lid == 0) shp[wid] = mxp;
        __syncthreads();
        if (wid == 0) {
            float v = (lid < NW) ? shp[lid] : -1e30f;
            #pragma unroll
            for (int off = 4; off > 0; off >>= 1)
                v = fmaxf(v, __shfl_xor_sync(0xffffffff, v, off));
            mxp = v;
        }
    }

    __shared__ bool s_last;
    if (threadIdx.x == 0) {
        float* dst = &g_part[(long)blockIdx.x * 5];
        dst[0] = sh[0][0]; dst[1] = sh[0][1]; dst[2] = sh[0][2];
        dst[3] = sh_blkmax; dst[4] = mxp;
        __threadfence();
        int old = atomicAdd(&g_count, 1);
        s_last = (old == NBLOCKS - 1);
    }
    __syncthreads();

    if (!s_last) return;

    // ---- fused epilogue: last block reduces all partials ----
    __shared__ float losses[BC];
    __shared__ float imgl[B_DIM];

    if (threadIdx.x < BC) {
        const int c = threadIdx.x;
        float a_d2t = 0.f, a_d2 = 0.f, a_t = 0.f;
        float a_mt = -1e30f, a_mp = -1e30f;
        #pragma unroll
        for (int j = 0; j < SPLIT; j++) {
            const float* src = &g_part[(long)(c * SPLIT + j) * 5];
            a_d2t += __ldcg(src + 0);
            a_d2  += __ldcg(src + 1);
            a_t   += __ldcg(src + 2);
            a_mt = fmaxf(a_mt, __ldcg(src + 3));
            a_mp = fmaxf(a_mp, __ldcg(src + 4));
        }
        float m1 = a_d2t;
        float m2 = a_d2 - a_d2t;
        float d1 = a_t;
        float d2 = (float)HW - a_t;
        float loss = ALPHA * m1 / (d1 + SMOOTH) + (1.0f - ALPHA) * m2 / (d2 + SMOOTH);
        bool active = !((a_mt == 0.0f) && (a_mp == 0.0f));
        losses[c] = active ? loss : 0.0f;
    }
    __syncthreads();

    if (threadIdx.x < B_DIM) {
        float s = 0.f, cnt = 0.f;
        #pragma unroll
        for (int c = 0; c < C_DIM; c++) {
            float v = losses[threadIdx.x * C_DIM + c];
            s += v;
            if (v != 0.0f) cnt += 1.0f;
        }
        imgl[threadIdx.x] = s / cnt;
    }
    __syncthreads();

    if (threadIdx.x == 0) {
        float s = 0.f;
        #pragma unroll
        for (int b = 0; b < B_DIM; b++) s += imgl[b];
        out[0] = s / (float)B_DIM;
        g_count = 0;   // reset for next graph replay (deterministic)
    }
}

extern "C" void kernel_launch(void* const* d_in, const int* in_sizes, int n_in,
                              void* d_out, int out_size)
{
    const float4* no = (const float4*)d_in[0];   // net_out
    const float4* tg = (const float4*)d_in[1];   // target
    const float4* mp = (const float4*)d_in[2];   // max_positiones

    fused_kernel<<<NBLOCKS, NTHREADS>>>(no, tg, mp, (float*)d_out);
}